// round 11
// baseline (speedup 1.0000x reference)
#include <cuda_runtime.h>
#include <cstdint>

// Problem constants
#define HH 64
#define WW 64
#define CC 3
#define NW 16
#define NPATCH 768
#define NCOMP 16
#define NBIN 200
#define NN 4096
#define DD 12288
#define TT 12288

#define ROWS_PER_BLOCK 512
#define ROW_BLOCKS (NN / ROWS_PER_BLOCK)   // 8
#define ITERS (ROWS_PER_BLOCK / 32)        // 16 (16 r-groups x 2 chains)

#define NCOMP3 48            // 3 channels x 16 comps per block
#define KSTRIDE 201          // padded stride: t*201 mod 32 cycles all residues
#define LUT_N 512
#define LUT_STRIDE 516       // bytes: 129 words

// dynamic shared layout (floats/bytes)
#define SX_OFF   0
#define SY_OFF   (NCOMP3 * KSTRIDE)                 // floats
#define SD_OFF   (2 * NCOMP3 * KSTRIDE)
#define TAB_FLOATS (3 * NCOMP3 * KSTRIDE)           // 28944 floats = 115776 B
#define LUT_BYTE_OFF (TAB_FLOATS * 4)               // 115776
#define SMEM_TOTAL (LUT_BYTE_OFF + NCOMP3 * LUT_STRIDE)   // 140544 B

// scratch (device globals: no allocation allowed)
__device__ uint8_t g_lut[TT * LUT_N];                 // 6.3 MB
__device__ float   g_logj_partial[NPATCH * NN];       // 12.6 MB
__device__ float   g_logj_p2[8 * NN];                 // 128 KB

// ---------------------------------------------------------------------------
// LUT build: per spline, lut[i] = count(knots < x0 + i*(xl-x0)/LUT_N)
// ---------------------------------------------------------------------------
__global__ __launch_bounds__(256)
void build_lut_kernel(const float* __restrict__ kx)
{
    __shared__ float s[NCOMP * NBIN];
    const int p = blockIdx.x;
    const int tid = threadIdx.x;
    for (int i = tid; i < NCOMP * NBIN; i += 256) s[i] = kx[p * NCOMP * NBIN + i];
    __syncthreads();

    for (int e = tid; e < NCOMP * LUT_N; e += 256) {
        const int c = e >> 9;
        const int i = e & (LUT_N - 1);
        const float* xx = s + c * NBIN;
        const float x0 = xx[0], xl = xx[NBIN - 1];
        const float gx = x0 + (xl - x0) * ((float)i * (1.0f / LUT_N));
        int lo = 0;
        #pragma unroll
        for (int st = 128; st > 0; st >>= 1) {
            int m = lo + st;
            if (m <= NBIN && xx[m - 1] < gx) lo = m;
        }
        g_lut[(p * NCOMP + c) * LUT_N + i] = (uint8_t)lo;
    }
}

// ---------------------------------------------------------------------------
// Per-element spline evaluation (branchless LUT search, scalar tables)
// ---------------------------------------------------------------------------
struct SpOut { float delta; float logd; };

__device__ __forceinline__ SpOut spline_eval(
    float X,
    const float* __restrict__ xxc, const float* __restrict__ yyc,
    const float* __restrict__ ddc, const uint8_t* __restrict__ lutc,
    float x0, float xl, float y0, float yl, float d0f, float dlf, float invstep)
{
    int li = __float2int_rd((X - x0) * invstep);
    li = min(max(li, 0), LUT_N - 1);
    int lo = lutc[li];
    lo -= ((lo > 0)    & (xxc[max(lo - 1, 0)] >= X));       // fp-edge back-probe
    lo += ((lo < NBIN) & (xxc[min(lo, NBIN - 1)] < X));     // fwd probe 1
    lo += ((lo < NBIN) & (xxc[min(lo, NBIN - 1)] < X));     // fwd probe 2
    lo += ((lo < NBIN) & (xxc[min(lo, NBIN - 1)] < X));     // fwd probe 3
    const int k = min(max(lo - 1, 0), NBIN - 2);

    const float xk = xxc[k], xk1 = xxc[k + 1];
    const float yk = yyc[k], yk1 = yyc[k + 1];
    const float dk = ddc[k], dk1 = ddc[k + 1];

    const float wx   = xk1 - xk;
    const float rwx  = __fdividef(1.f, wx);
    const float s_   = (yk1 - yk) * rwx;
    const float xi   = __saturatef((X - xk) * rwx);
    const float xi1  = 1.f - xi;
    const float xixi1 = xi * xi1;
    const float den  = fmaf(dk + dk1 - 2.f * s_, xixi1, s_);
    const float rden = __fdividef(1.f, den);
    const float num  = fmaf(s_ * xi, xi, dk * xixi1);
    float y    = fmaf(yk1 - yk, num * rden, yk);
    const float dnum = fmaf(dk1 * xi, xi, fmaf(2.f * s_, xixi1, dk * xi1 * xi1));
    float dydx = (s_ * s_) * dnum * (rden * rden);

    const bool below = X < x0;
    const bool above = X > xl;
    if (below) { y = fmaf(X - x0, d0f, y0); dydx = d0f; }
    else if (above) { y = fmaf(X - xl, dlf, yl); dydx = dlf; }

    SpOut o;
    o.delta = y - X;
    o.logd  = __logf(dydx);
    return o;
}

// ---------------------------------------------------------------------------
// Main transport kernel — channel-fused (3 patches/block), warp-synchronous
// ---------------------------------------------------------------------------
__global__ __launch_bounds__(768, 1)
void patch_transport_kernel(const float* __restrict__ data,
                            const float* __restrict__ wT,
                            const float* __restrict__ kx,
                            const float* __restrict__ ky,
                            const float* __restrict__ kd,
                            float* __restrict__ out)
{
    extern __shared__ float smemf[];
    float*   sx   = smemf + SX_OFF;
    float*   sy   = smemf + SY_OFF;
    float*   sd   = smemf + SD_OFF;
    uint8_t* slut = (uint8_t*)smemf + LUT_BYTE_OFF;

    const int pg  = blockIdx.x;           // patch-group 0..255 (ph*16+pw)
    const int tid = threadIdx.x;

    // ---- stage knots + LUT for the 3 channel-patches (contiguous in global) ----
    {
        const int tbase = pg * NCOMP3 * NBIN;    // pg*9600
        for (int i = tid; i < NCOMP3 * NBIN; i += 768) {
            const int t = i / NBIN, j = i - t * NBIN;
            const int di = t * KSTRIDE + j;
            sx[di] = kx[tbase + i];
            sy[di] = ky[tbase + i];
            sd[di] = kd[tbase + i];
        }
        const uint32_t* gl32 = (const uint32_t*)(g_lut + (size_t)pg * NCOMP3 * LUT_N);
        for (int e = tid; e < NCOMP3 * (LUT_N / 4); e += 768) {
            const int t = e >> 7, w = e & 127;
            *(uint32_t*)&slut[t * LUT_STRIDE + w * 4] = gl32[t * 128 + w];
        }
    }

    const int lane = tid & 31;
    const int g    = tid >> 4;            // group 0..47
    const int c    = lane & 15;           // component / element index
    const int ch   = g % 3;               // channel
    const int r    = g / 3;               // row slot 0..15
    const int t    = ch * NCOMP + c;      // spline index within block
    const int p    = pg * 3 + ch;         // global patch index

    // weights in registers: column c (forward), row c (backward)
    float wc[16], wr[16];
    #pragma unroll
    for (int k = 0; k < 16; ++k) wc[k] = wT[p * 256 + k * 16 + c];
    #pragma unroll
    for (int k = 0; k < 16; ++k) wr[k] = wT[p * 256 + c * 16 + k];

    __syncthreads();   // the ONLY block barrier

    // patch -> flat image offset for this thread's element
    const int ph  = pg / NW;
    const int pw  = pg % NW;
    const int base = ph * (4 * WW * CC) + pw * (4 * CC) + ch;
    const int offc = base + (c >> 2) * (WW * CC) + (c & 3) * CC;

    const float*   __restrict__ xxc  = sx + t * KSTRIDE;
    const float*   __restrict__ yyc  = sy + t * KSTRIDE;
    const float*   __restrict__ ddc  = sd + t * KSTRIDE;
    const uint8_t* __restrict__ lutc = slut + t * LUT_STRIDE;

    const float x0 = xxc[0], xl = xxc[NBIN - 1];
    const float y0 = yyc[0], yl = yyc[NBIN - 1];
    const float d0f = ddc[0], dlf = ddc[NBIN - 1];
    const float invstep = (float)LUT_N / (xl - x0);

    const int rowbase = blockIdx.y * ROWS_PER_BLOCK;

    int n = rowbase + r;                  // chain A row; chain B = n+16
    float pvA = data[(size_t)n * DD + offc];
    float pvB = data[(size_t)(n + 16) * DD + offc];

    for (int it = 0; it < ITERS; ++it) {
        const int nA = n;
        const float paA = pvA, paB = pvB;
        n += 32;
        if (it + 1 < ITERS) {
            pvA = data[(size_t)n * DD + offc];
            pvB = data[(size_t)(n + 16) * DD + offc];
        }

        // forward projections (2 chains), 2-way split accumulators
        float XA0 = 0.f, XA1 = 0.f, XB0 = 0.f, XB1 = 0.f;
        #pragma unroll
        for (int k = 0; k < 8; ++k) {
            XA0 = fmaf(__shfl_sync(0xffffffffu, paA, k,     16), wc[k],     XA0);
            XA1 = fmaf(__shfl_sync(0xffffffffu, paA, k + 8, 16), wc[k + 8], XA1);
            XB0 = fmaf(__shfl_sync(0xffffffffu, paB, k,     16), wc[k],     XB0);
            XB1 = fmaf(__shfl_sync(0xffffffffu, paB, k + 8, 16), wc[k + 8], XB1);
        }
        const float XA = XA0 + XA1;
        const float XB = XB0 + XB1;

        const SpOut oA = spline_eval(XA, xxc, yyc, ddc, lutc, x0, xl, y0, yl, d0f, dlf, invstep);
        const SpOut oB = spline_eval(XB, xxc, yyc, ddc, lutc, x0, xl, y0, yl, d0f, dlf, invstep);

        // reduce logd over the 16 lanes of each half-warp (both chains)
        float logdA = oA.logd, logdB = oB.logd;
        #pragma unroll
        for (int ofs = 8; ofs > 0; ofs >>= 1) {
            logdA += __shfl_xor_sync(0xffffffffu, logdA, ofs, 16);
            logdB += __shfl_xor_sync(0xffffffffu, logdB, ofs, 16);
        }

        // backward projections: dpatch[c] = sum_cc delta[cc] * wT[p, c, cc]
        float dA0 = 0.f, dA1 = 0.f, dB0 = 0.f, dB1 = 0.f;
        #pragma unroll
        for (int cc = 0; cc < 8; ++cc) {
            dA0 = fmaf(__shfl_sync(0xffffffffu, oA.delta, cc,     16), wr[cc],     dA0);
            dA1 = fmaf(__shfl_sync(0xffffffffu, oA.delta, cc + 8, 16), wr[cc + 8], dA1);
            dB0 = fmaf(__shfl_sync(0xffffffffu, oB.delta, cc,     16), wr[cc],     dB0);
            dB1 = fmaf(__shfl_sync(0xffffffffu, oB.delta, cc + 8, 16), wr[cc + 8], dB1);
        }

        out[(size_t)nA * DD + offc]        = paA + (dA0 + dA1);
        out[(size_t)(nA + 16) * DD + offc] = paB + (dB0 + dB1);

        if (c == 0) {
            g_logj_partial[p * NN + nA]      = logdA;
            g_logj_partial[p * NN + nA + 16] = logdB;
        }
    }
}

// ---------------------------------------------------------------------------
// log-Jacobian reduction, two stages
// ---------------------------------------------------------------------------
__global__ __launch_bounds__(256)
void logj_reduce1(void)
{
    const int n  = blockIdx.x * 256 + threadIdx.x;
    const int p0 = blockIdx.y * (NPATCH / 8);
    float s0 = 0.f, s1 = 0.f, s2 = 0.f, s3 = 0.f;
    #pragma unroll 4
    for (int p = p0; p < p0 + NPATCH / 8; p += 4) {
        s0 += g_logj_partial[(p + 0) * NN + n];
        s1 += g_logj_partial[(p + 1) * NN + n];
        s2 += g_logj_partial[(p + 2) * NN + n];
        s3 += g_logj_partial[(p + 3) * NN + n];
    }
    g_logj_p2[blockIdx.y * NN + n] = (s0 + s1) + (s2 + s3);
}

__global__ __launch_bounds__(256)
void logj_reduce2(float* __restrict__ out)
{
    const int n = blockIdx.x * 256 + threadIdx.x;
    float s = 0.f;
    #pragma unroll
    for (int g = 0; g < 8; ++g) s += g_logj_p2[g * NN + n];
    out[(size_t)NN * DD + n] = s;
}

extern "C" void kernel_launch(void* const* d_in, const int* in_sizes, int n_in,
                              void* d_out, int out_size)
{
    const float* data = (const float*)d_in[0];
    const float* wT   = (const float*)d_in[1];
    const float* kx   = (const float*)d_in[2];
    const float* ky   = (const float*)d_in[3];
    const float* kd   = (const float*)d_in[4];
    float* out = (float*)d_out;

    cudaFuncSetAttribute(patch_transport_kernel,
                         cudaFuncAttributeMaxDynamicSharedMemorySize, SMEM_TOTAL);

    build_lut_kernel<<<NPATCH, 256>>>(kx);
    dim3 grid(NPATCH / 3, ROW_BLOCKS);
    patch_transport_kernel<<<grid, 768, SMEM_TOTAL>>>(data, wT, kx, ky, kd, out);
    logj_reduce1<<<dim3(NN / 256, 8), 256>>>();
    logj_reduce2<<<NN / 256, 256>>>(out);
}

// round 13
// speedup vs baseline: 1.1703x; 1.1703x over previous
#include <cuda_runtime.h>
#include <cstdint>

// Problem constants
#define HH 64
#define WW 64
#define CC 3
#define NW 16
#define NPATCH 768
#define NCOMP 16
#define NBIN 200
#define NN 4096
#define DD 12288
#define TT 12288

#define ROWS_PER_BLOCK 512
#define ROW_BLOCKS (NN / ROWS_PER_BLOCK)   // 8
#define ITERS (ROWS_PER_BLOCK / 32)        // 16 (2 rows/warp/chain, 2 chains)

#define KSTRIDE 201          // padded stride: c*201 mod 32 -> 16 distinct residues
#define LUT_N 512
#define LUT_STRIDE 516       // bytes

// dynamic shared layout
#define SX_OFF   0                              // floats
#define SY_OFF   (NCOMP * KSTRIDE)              // 3216
#define SD_OFF   (2 * NCOMP * KSTRIDE)          // 6432
#define TAB_FLOATS (3 * NCOMP * KSTRIDE)        // 9648 floats = 38592 B
#define LUT_BYTE_OFF (TAB_FLOATS * 4)           // 38592
#define LUT_BYTES (NCOMP * LUT_STRIDE)          // 8256
#define PV_FLOAT_OFF ((LUT_BYTE_OFF + LUT_BYTES) / 4)   // 11712 (16B aligned)
#define PV_FLOATS (8 * 2 * 2 * 32)              // 1024: [warp][parity][chain][32]
#define DB_FLOAT_OFF (PV_FLOAT_OFF + PV_FLOATS) // 12736
#define DB_FLOATS (8 * 2 * 2 * 32)              // 1024
#define SMEM_TOTAL ((DB_FLOAT_OFF + DB_FLOATS) * 4)     // 55040 B

// scratch (device global: no allocation allowed)
__device__ uint8_t g_lut[TT * LUT_N];           // 6.3 MB

// ---------------------------------------------------------------------------
// Zero the logj slice of out (poisoned by harness)
// ---------------------------------------------------------------------------
__global__ __launch_bounds__(256)
void init_logj_kernel(float* __restrict__ out)
{
    const int n = blockIdx.x * 256 + threadIdx.x;
    out[(size_t)NN * DD + n] = 0.f;
}

// ---------------------------------------------------------------------------
// LUT build: per spline, lut[i] = count(knots < x0 + i*(xl-x0)/LUT_N)
// ---------------------------------------------------------------------------
__global__ __launch_bounds__(256)
void build_lut_kernel(const float* __restrict__ kx)
{
    __shared__ float s[NCOMP * NBIN];
    const int p = blockIdx.x;
    const int tid = threadIdx.x;
    for (int i = tid; i < NCOMP * NBIN; i += 256) s[i] = kx[p * NCOMP * NBIN + i];
    __syncthreads();

    for (int e = tid; e < NCOMP * LUT_N; e += 256) {
        const int c = e >> 9;
        const int i = e & (LUT_N - 1);
        const float* xx = s + c * NBIN;
        const float x0 = xx[0], xl = xx[NBIN - 1];
        const float gx = x0 + (xl - x0) * ((float)i * (1.0f / LUT_N));
        int lo = 0;
        #pragma unroll
        for (int st = 128; st > 0; st >>= 1) {
            int m = lo + st;
            if (m <= NBIN && xx[m - 1] < gx) lo = m;
        }
        g_lut[(p * NCOMP + c) * LUT_N + i] = (uint8_t)lo;
    }
}

// ---------------------------------------------------------------------------
// Per-element spline evaluation (branchless LUT search, scalar tables)
// ---------------------------------------------------------------------------
struct SpOut { float delta; float logd; };

__device__ __forceinline__ SpOut spline_eval(
    float X,
    const float* __restrict__ xxc, const float* __restrict__ yyc,
    const float* __restrict__ ddc, const uint8_t* __restrict__ lutc,
    float x0, float xl, float y0, float yl, float d0f, float dlf, float invstep)
{
    int li = __float2int_rd((X - x0) * invstep);
    li = min(max(li, 0), LUT_N - 1);
    int lo = lutc[li];
    lo -= ((lo > 0)    & (xxc[max(lo - 1, 0)] >= X));       // fp-edge back-probe
    lo += ((lo < NBIN) & (xxc[min(lo, NBIN - 1)] < X));     // fwd probe 1
    lo += ((lo < NBIN) & (xxc[min(lo, NBIN - 1)] < X));     // fwd probe 2
    lo += ((lo < NBIN) & (xxc[min(lo, NBIN - 1)] < X));     // fwd probe 3
    const int k = min(max(lo - 1, 0), NBIN - 2);

    const float xk = xxc[k], xk1 = xxc[k + 1];
    const float yk = yyc[k], yk1 = yyc[k + 1];
    const float dk = ddc[k], dk1 = ddc[k + 1];

    const float wx   = xk1 - xk;
    const float rwx  = __fdividef(1.f, wx);
    const float s_   = (yk1 - yk) * rwx;
    const float xi   = __saturatef((X - xk) * rwx);
    const float xi1  = 1.f - xi;
    const float xixi1 = xi * xi1;
    const float den  = fmaf(dk + dk1 - 2.f * s_, xixi1, s_);
    const float rden = __fdividef(1.f, den);
    const float num  = fmaf(s_ * xi, xi, dk * xixi1);
    float y    = fmaf(yk1 - yk, num * rden, yk);
    const float dnum = fmaf(dk1 * xi, xi, fmaf(2.f * s_, xixi1, dk * xi1 * xi1));
    float dydx = (s_ * s_) * dnum * (rden * rden);

    const bool below = X < x0;
    const bool above = X > xl;
    if (below) { y = fmaf(X - x0, d0f, y0); dydx = d0f; }
    else if (above) { y = fmaf(X - xl, dlf, yl); dydx = dlf; }

    SpOut o;
    o.delta = y - X;
    o.logd  = __logf(dydx);
    return o;
}

// ---------------------------------------------------------------------------
// Main transport kernel — warp-shared exchange matmuls, atomic logj
// ---------------------------------------------------------------------------
__global__ __launch_bounds__(256, 3)
void patch_transport_kernel(const float* __restrict__ data,
                            const float* __restrict__ wT,
                            const float* __restrict__ kx,
                            const float* __restrict__ ky,
                            const float* __restrict__ kd,
                            float* __restrict__ out)
{
    extern __shared__ float smemf[];
    float*   sx    = smemf + SX_OFF;
    float*   sy    = smemf + SY_OFF;
    float*   sd    = smemf + SD_OFF;
    uint8_t* slut  = (uint8_t*)smemf + LUT_BYTE_OFF;
    float*   pvex  = smemf + PV_FLOAT_OFF;      // [warp][parity][chain][32]
    float*   dbex  = smemf + DB_FLOAT_OFF;

    const int p   = blockIdx.x;
    const int tid = threadIdx.x;

    // ---- stage knots + LUT ----
    {
        const int tbase = p * NCOMP * NBIN;
        for (int i = tid; i < NCOMP * NBIN; i += 256) {
            const int c2 = i / NBIN, j = i - c2 * NBIN;
            const int di = c2 * KSTRIDE + j;
            sx[di] = kx[tbase + i];
            sy[di] = ky[tbase + i];
            sd[di] = kd[tbase + i];
        }
        const uint32_t* gl32 = (const uint32_t*)(g_lut + (size_t)p * NCOMP * LUT_N);
        for (int e = tid; e < NCOMP * (LUT_N / 4); e += 256) {
            const int c2 = e >> 7, w = e & 127;
            *(uint32_t*)&slut[c2 * LUT_STRIDE + w * 4] = gl32[c2 * 128 + w];
        }
    }

    const int lane = tid & 31;
    const int wid  = tid >> 5;
    const int half = lane >> 4;
    const int c    = lane & 15;

    // weights in registers: column c (forward), row c (backward)
    float wc[16], wr[16];
    #pragma unroll
    for (int k = 0; k < 16; ++k) wc[k] = wT[p * 256 + k * 16 + c];
    #pragma unroll
    for (int k = 0; k < 16; ++k) wr[k] = wT[p * 256 + c * 16 + k];

    __syncthreads();   // the ONLY block barrier

    // patch -> flat image offset for this thread's element
    const int ph  = p / (NW * CC);
    const int rem = p % (NW * CC);
    const int pw  = rem / CC;
    const int ch  = rem % CC;
    const int base = ph * (4 * WW * CC) + pw * (4 * CC) + ch;
    const int offc = base + (c >> 2) * (WW * CC) + (c & 3) * CC;

    const float*   __restrict__ xxc  = sx + c * KSTRIDE;
    const float*   __restrict__ yyc  = sy + c * KSTRIDE;
    const float*   __restrict__ ddc  = sd + c * KSTRIDE;
    const uint8_t* __restrict__ lutc = slut + c * LUT_STRIDE;

    const float x0 = xxc[0], xl = xxc[NBIN - 1];
    const float y0 = yyc[0], yl = yyc[NBIN - 1];
    const float d0f = ddc[0], dlf = ddc[NBIN - 1];
    const float invstep = (float)LUT_N / (xl - x0);

    const int rowbase = blockIdx.y * ROWS_PER_BLOCK;
    const int rsub = wid * 2 + half;            // 0..15

    float* pvw = pvex + wid * 128;              // this warp's pv exchange
    float* dbw = dbex + wid * 128;              // this warp's delta exchange
    const int slot = half * 16 + c;

    int n = rowbase + rsub;                     // chain A row; chain B = n+16
    float pvA = data[(size_t)n * DD + offc];
    float pvB = data[(size_t)(n + 16) * DD + offc];

    float* logj = out + (size_t)NN * DD;

    for (int it = 0; it < ITERS; ++it) {
        const int par = it & 1;
        const int nA = n;
        const float paA = pvA, paB = pvB;
        n += 32;
        if (it + 1 < ITERS) {
            pvA = data[(size_t)n * DD + offc];
            pvB = data[(size_t)(n + 16) * DD + offc];
        }

        // exchange patch values (parity double-buffered)
        float* pvp = pvw + par * 64;
        pvp[slot]      = paA;
        pvp[32 + slot] = paB;
        __syncwarp();

        // forward: X = patch_row . w_col(c) via broadcast LDS.128
        const float4* rA = (const float4*)(pvp + half * 16);
        const float4* rB = (const float4*)(pvp + 32 + half * 16);
        float XA = 0.f, XB = 0.f;
        #pragma unroll
        for (int q = 0; q < 4; ++q) {
            const float4 a = rA[q];
            const float4 b = rB[q];
            XA = fmaf(a.x, wc[4*q+0], XA); XA = fmaf(a.y, wc[4*q+1], XA);
            XA = fmaf(a.z, wc[4*q+2], XA); XA = fmaf(a.w, wc[4*q+3], XA);
            XB = fmaf(b.x, wc[4*q+0], XB); XB = fmaf(b.y, wc[4*q+1], XB);
            XB = fmaf(b.z, wc[4*q+2], XB); XB = fmaf(b.w, wc[4*q+3], XB);
        }

        const SpOut oA = spline_eval(XA, xxc, yyc, ddc, lutc, x0, xl, y0, yl, d0f, dlf, invstep);
        const SpOut oB = spline_eval(XB, xxc, yyc, ddc, lutc, x0, xl, y0, yl, d0f, dlf, invstep);

        // reduce logd over the 16 lanes of each half-warp
        float logdA = oA.logd, logdB = oB.logd;
        #pragma unroll
        for (int ofs = 8; ofs > 0; ofs >>= 1) {
            logdA += __shfl_xor_sync(0xffffffffu, logdA, ofs, 16);
            logdB += __shfl_xor_sync(0xffffffffu, logdB, ofs, 16);
        }

        // exchange deltas (parity double-buffered)
        float* dbp = dbw + par * 64;
        dbp[slot]      = oA.delta;
        dbp[32 + slot] = oB.delta;
        __syncwarp();

        // backward: dpatch[c] = delta_row . wT[p, c, :] via broadcast LDS.128
        const float4* eA = (const float4*)(dbp + half * 16);
        const float4* eB = (const float4*)(dbp + 32 + half * 16);
        float dpA = 0.f, dpB = 0.f;
        #pragma unroll
        for (int q = 0; q < 4; ++q) {
            const float4 a = eA[q];
            const float4 b = eB[q];
            dpA = fmaf(a.x, wr[4*q+0], dpA); dpA = fmaf(a.y, wr[4*q+1], dpA);
            dpA = fmaf(a.z, wr[4*q+2], dpA); dpA = fmaf(a.w, wr[4*q+3], dpA);
            dpB = fmaf(b.x, wr[4*q+0], dpB); dpB = fmaf(b.y, wr[4*q+1], dpB);
            dpB = fmaf(b.z, wr[4*q+2], dpB); dpB = fmaf(b.w, wr[4*q+3], dpB);
        }

        out[(size_t)nA * DD + offc]        = paA + dpA;
        out[(size_t)(nA + 16) * DD + offc] = paB + dpB;

        if (c == 0) {
            atomicAdd(&logj[nA],      logdA);
            atomicAdd(&logj[nA + 16], logdB);
        }
    }
}

extern "C" void kernel_launch(void* const* d_in, const int* in_sizes, int n_in,
                              void* d_out, int out_size)
{
    const float* data = (const float*)d_in[0];
    const float* wT   = (const float*)d_in[1];
    const float* kx   = (const float*)d_in[2];
    const float* ky   = (const float*)d_in[3];
    const float* kd   = (const float*)d_in[4];
    float* out = (float*)d_out;

    cudaFuncSetAttribute(patch_transport_kernel,
                         cudaFuncAttributeMaxDynamicSharedMemorySize, SMEM_TOTAL);

    init_logj_kernel<<<NN / 256, 256>>>(out);
    build_lut_kernel<<<NPATCH, 256>>>(kx);
    dim3 grid(NPATCH, ROW_BLOCKS);
    patch_transport_kernel<<<grid, 256, SMEM_TOTAL>>>(data, wT, kx, ky, kd, out);
}

// round 14
// speedup vs baseline: 1.2183x; 1.0410x over previous
#include <cuda_runtime.h>
#include <cstdint>

// Problem constants
#define HH 64
#define WW 64
#define CC 3
#define NW 16
#define NPATCH 768
#define NCOMP 16
#define NBIN 200
#define NN 4096
#define DD 12288
#define TT 12288

#define ROWS_PER_BLOCK 512
#define ROW_BLOCKS (NN / ROWS_PER_BLOCK)   // 8
#define ITERS (ROWS_PER_BLOCK / 32)        // 16 (2 rows/warp/chain, 2 chains)

#define KSTRIDE 201          // padded stride: c*201 mod 32 -> 16 distinct residues
#define LUT_N 512
#define LUT_STRIDE 516       // bytes

// dynamic shared layout
#define SX_OFF   0                              // floats
#define SY_OFF   (NCOMP * KSTRIDE)              // 3216
#define SD_OFF   (2 * NCOMP * KSTRIDE)          // 6432
#define TAB_FLOATS (3 * NCOMP * KSTRIDE)        // 9648 floats = 38592 B
#define LUT_BYTE_OFF (TAB_FLOATS * 4)           // 38592
#define LUT_BYTES (NCOMP * LUT_STRIDE)          // 8256
#define PV_FLOAT_OFF ((LUT_BYTE_OFF + LUT_BYTES) / 4)   // 11712 (16B aligned)
#define PV_FLOATS (8 * 2 * 2 * 32)              // 1024: [warp][parity][chain][32]
#define DB_FLOAT_OFF (PV_FLOAT_OFF + PV_FLOATS) // 12736
#define DB_FLOATS (8 * 2 * 2 * 32)              // 1024
#define SMEM_TOTAL ((DB_FLOAT_OFF + DB_FLOATS) * 4)     // 55040 B

// scratch (device global: no allocation allowed)
__device__ uint8_t g_lut[TT * LUT_N];           // 6.3 MB

// ---------------------------------------------------------------------------
// Zero the logj slice of out (poisoned by harness)
// ---------------------------------------------------------------------------
__global__ __launch_bounds__(256)
void init_logj_kernel(float* __restrict__ out)
{
    const int n = blockIdx.x * 256 + threadIdx.x;
    out[(size_t)NN * DD + n] = 0.f;
}

// ---------------------------------------------------------------------------
// LUT build: per spline, lut[i] = count(knots < x0 + i*(xl-x0)/LUT_N)
// ---------------------------------------------------------------------------
__global__ __launch_bounds__(256)
void build_lut_kernel(const float* __restrict__ kx)
{
    __shared__ float s[NCOMP * NBIN];
    const int p = blockIdx.x;
    const int tid = threadIdx.x;
    for (int i = tid; i < NCOMP * NBIN; i += 256) s[i] = kx[p * NCOMP * NBIN + i];
    __syncthreads();

    for (int e = tid; e < NCOMP * LUT_N; e += 256) {
        const int c = e >> 9;
        const int i = e & (LUT_N - 1);
        const float* xx = s + c * NBIN;
        const float x0 = xx[0], xl = xx[NBIN - 1];
        const float gx = x0 + (xl - x0) * ((float)i * (1.0f / LUT_N));
        int lo = 0;
        #pragma unroll
        for (int st = 128; st > 0; st >>= 1) {
            int m = lo + st;
            if (m <= NBIN && xx[m - 1] < gx) lo = m;
        }
        g_lut[(p * NCOMP + c) * LUT_N + i] = (uint8_t)lo;
    }
}

// ---------------------------------------------------------------------------
// Per-element spline evaluation — single-level parallel probe search
// ---------------------------------------------------------------------------
struct SpOut { float delta; float logd; };

__device__ __forceinline__ SpOut spline_eval(
    float X,
    const float* __restrict__ xxc, const float* __restrict__ yyc,
    const float* __restrict__ ddc, const uint8_t* __restrict__ lutc,
    float x0, float xl, float y0, float yl, float d0f, float dlf, float invstep)
{
    int li = __float2int_rd((X - x0) * invstep);
    li = min(max(li, 0), LUT_N - 1);
    const int lo0 = lutc[li];

    // neighborhood loads — all independent (one LDS latency level)
    const float xm1 = xxc[max(lo0 - 1, 0)];
    const float xp0 = xxc[min(lo0,     NBIN - 1)];
    const float xp1 = xxc[min(lo0 + 1, NBIN - 1)];
    const float xp2 = xxc[min(lo0 + 2, NBIN - 1)];

    // closed form of [1 back-probe; 3 sequential fwd probes]:
    // if back-probe fires, fwd probes re-test xm1 (>=X) and never advance.
    const int b  = (lo0 > 0) & (xm1 >= X);
    const int a1 = (lo0 < NBIN)       & (xp0 < X);
    const int a2 = a1 & ((lo0 + 1) < NBIN) & (xp1 < X);
    const int a3 = a2 & ((lo0 + 2) < NBIN) & (xp2 < X);
    const int lo = b ? (lo0 - 1) : (lo0 + a1 + a2 + a3);
    const int k = min(max(lo - 1, 0), NBIN - 2);

    const float xk = xxc[k], xk1 = xxc[k + 1];
    const float yk = yyc[k], yk1 = yyc[k + 1];
    const float dk = ddc[k], dk1 = ddc[k + 1];

    const float wx   = xk1 - xk;
    const float rwx  = __fdividef(1.f, wx);
    const float s_   = (yk1 - yk) * rwx;
    const float xi   = __saturatef((X - xk) * rwx);
    const float xi1  = 1.f - xi;
    const float xixi1 = xi * xi1;
    const float den  = fmaf(dk + dk1 - 2.f * s_, xixi1, s_);
    const float rden = __fdividef(1.f, den);
    const float num  = fmaf(s_ * xi, xi, dk * xixi1);
    float y    = fmaf(yk1 - yk, num * rden, yk);
    const float dnum = fmaf(dk1 * xi, xi, fmaf(2.f * s_, xixi1, dk * xi1 * xi1));
    float dydx = (s_ * s_) * dnum * (rden * rden);

    const bool below = X < x0;
    const bool above = X > xl;
    if (below) { y = fmaf(X - x0, d0f, y0); dydx = d0f; }
    else if (above) { y = fmaf(X - xl, dlf, yl); dydx = dlf; }

    SpOut o;
    o.delta = y - X;
    o.logd  = __logf(dydx);
    return o;
}

// ---------------------------------------------------------------------------
// Main transport kernel — warp-shared exchange matmuls, atomic logj
// ---------------------------------------------------------------------------
__global__ __launch_bounds__(256, 3)
void patch_transport_kernel(const float* __restrict__ data,
                            const float* __restrict__ wT,
                            const float* __restrict__ kx,
                            const float* __restrict__ ky,
                            const float* __restrict__ kd,
                            float* __restrict__ out)
{
    extern __shared__ float smemf[];
    float*   sx    = smemf + SX_OFF;
    float*   sy    = smemf + SY_OFF;
    float*   sd    = smemf + SD_OFF;
    uint8_t* slut  = (uint8_t*)smemf + LUT_BYTE_OFF;
    float*   pvex  = smemf + PV_FLOAT_OFF;      // [warp][parity][chain][32]
    float*   dbex  = smemf + DB_FLOAT_OFF;

    const int p   = blockIdx.x;
    const int tid = threadIdx.x;

    // ---- stage knots + LUT ----
    {
        const int tbase = p * NCOMP * NBIN;
        for (int i = tid; i < NCOMP * NBIN; i += 256) {
            const int c2 = i / NBIN, j = i - c2 * NBIN;
            const int di = c2 * KSTRIDE + j;
            sx[di] = kx[tbase + i];
            sy[di] = ky[tbase + i];
            sd[di] = kd[tbase + i];
        }
        const uint32_t* gl32 = (const uint32_t*)(g_lut + (size_t)p * NCOMP * LUT_N);
        for (int e = tid; e < NCOMP * (LUT_N / 4); e += 256) {
            const int c2 = e >> 7, w = e & 127;
            *(uint32_t*)&slut[c2 * LUT_STRIDE + w * 4] = gl32[c2 * 128 + w];
        }
    }

    const int lane = tid & 31;
    const int wid  = tid >> 5;
    const int half = lane >> 4;
    const int c    = lane & 15;

    // weights in registers: column c (forward), row c (backward)
    float wc[16], wr[16];
    #pragma unroll
    for (int k = 0; k < 16; ++k) wc[k] = wT[p * 256 + k * 16 + c];
    #pragma unroll
    for (int k = 0; k < 16; ++k) wr[k] = wT[p * 256 + c * 16 + k];

    __syncthreads();   // the ONLY block barrier

    // patch -> flat image offset for this thread's element
    const int ph  = p / (NW * CC);
    const int rem = p % (NW * CC);
    const int pw  = rem / CC;
    const int ch  = rem % CC;
    const int base = ph * (4 * WW * CC) + pw * (4 * CC) + ch;
    const int offc = base + (c >> 2) * (WW * CC) + (c & 3) * CC;

    const float*   __restrict__ xxc  = sx + c * KSTRIDE;
    const float*   __restrict__ yyc  = sy + c * KSTRIDE;
    const float*   __restrict__ ddc  = sd + c * KSTRIDE;
    const uint8_t* __restrict__ lutc = slut + c * LUT_STRIDE;

    const float x0 = xxc[0], xl = xxc[NBIN - 1];
    const float y0 = yyc[0], yl = yyc[NBIN - 1];
    const float d0f = ddc[0], dlf = ddc[NBIN - 1];
    const float invstep = (float)LUT_N / (xl - x0);

    const int rowbase = blockIdx.y * ROWS_PER_BLOCK;
    const int rsub = wid * 2 + half;            // 0..15

    float* pvw = pvex + wid * 128;              // this warp's pv exchange
    float* dbw = dbex + wid * 128;              // this warp's delta exchange
    const int slot = half * 16 + c;

    int n = rowbase + rsub;                     // chain A row; chain B = n+16
    float pvA = data[(size_t)n * DD + offc];
    float pvB = data[(size_t)(n + 16) * DD + offc];

    float* logj = out + (size_t)NN * DD;

    for (int it = 0; it < ITERS; ++it) {
        const int par = it & 1;
        const int nA = n;
        const float paA = pvA, paB = pvB;
        n += 32;
        if (it + 1 < ITERS) {
            pvA = data[(size_t)n * DD + offc];
            pvB = data[(size_t)(n + 16) * DD + offc];
        }

        // exchange patch values (parity double-buffered)
        float* pvp = pvw + par * 64;
        pvp[slot]      = paA;
        pvp[32 + slot] = paB;
        __syncwarp();

        // forward: X = patch_row . w_col(c) via broadcast LDS.128
        const float4* rA = (const float4*)(pvp + half * 16);
        const float4* rB = (const float4*)(pvp + 32 + half * 16);
        float XA = 0.f, XB = 0.f;
        #pragma unroll
        for (int q = 0; q < 4; ++q) {
            const float4 a = rA[q];
            const float4 b = rB[q];
            XA = fmaf(a.x, wc[4*q+0], XA); XA = fmaf(a.y, wc[4*q+1], XA);
            XA = fmaf(a.z, wc[4*q+2], XA); XA = fmaf(a.w, wc[4*q+3], XA);
            XB = fmaf(b.x, wc[4*q+0], XB); XB = fmaf(b.y, wc[4*q+1], XB);
            XB = fmaf(b.z, wc[4*q+2], XB); XB = fmaf(b.w, wc[4*q+3], XB);
        }

        const SpOut oA = spline_eval(XA, xxc, yyc, ddc, lutc, x0, xl, y0, yl, d0f, dlf, invstep);
        const SpOut oB = spline_eval(XB, xxc, yyc, ddc, lutc, x0, xl, y0, yl, d0f, dlf, invstep);

        // exchange deltas (parity double-buffered)
        float* dbp = dbw + par * 64;
        dbp[slot]      = oA.delta;
        dbp[32 + slot] = oB.delta;
        __syncwarp();

        // backward: dpatch[c] = delta_row . wT[p, c, :] via broadcast LDS.128
        const float4* eA = (const float4*)(dbp + half * 16);
        const float4* eB = (const float4*)(dbp + 32 + half * 16);
        float dpA = 0.f, dpB = 0.f;
        #pragma unroll
        for (int q = 0; q < 4; ++q) {
            const float4 a = eA[q];
            const float4 b = eB[q];
            dpA = fmaf(a.x, wr[4*q+0], dpA); dpA = fmaf(a.y, wr[4*q+1], dpA);
            dpA = fmaf(a.z, wr[4*q+2], dpA); dpA = fmaf(a.w, wr[4*q+3], dpA);
            dpB = fmaf(b.x, wr[4*q+0], dpB); dpB = fmaf(b.y, wr[4*q+1], dpB);
            dpB = fmaf(b.z, wr[4*q+2], dpB); dpB = fmaf(b.w, wr[4*q+3], dpB);
        }

        out[(size_t)nA * DD + offc]        = paA + dpA;
        out[(size_t)(nA + 16) * DD + offc] = paB + dpB;

        // logd reductions off the store path
        float logdA = oA.logd, logdB = oB.logd;
        #pragma unroll
        for (int ofs = 8; ofs > 0; ofs >>= 1) {
            logdA += __shfl_xor_sync(0xffffffffu, logdA, ofs, 16);
            logdB += __shfl_xor_sync(0xffffffffu, logdB, ofs, 16);
        }
        if (c == 0) {
            atomicAdd(&logj[nA],      logdA);
            atomicAdd(&logj[nA + 16], logdB);
        }
    }
}

extern "C" void kernel_launch(void* const* d_in, const int* in_sizes, int n_in,
                              void* d_out, int out_size)
{
    const float* data = (const float*)d_in[0];
    const float* wT   = (const float*)d_in[1];
    const float* kx   = (const float*)d_in[2];
    const float* ky   = (const float*)d_in[3];
    const float* kd   = (const float*)d_in[4];
    float* out = (float*)d_out;

    cudaFuncSetAttribute(patch_transport_kernel,
                         cudaFuncAttributeMaxDynamicSharedMemorySize, SMEM_TOTAL);

    init_logj_kernel<<<NN / 256, 256>>>(out);
    build_lut_kernel<<<NPATCH, 256>>>(kx);
    dim3 grid(NPATCH, ROW_BLOCKS);
    patch_transport_kernel<<<grid, 256, SMEM_TOTAL>>>(data, wT, kx, ky, kd, out);
}